// round 1
// baseline (speedup 1.0000x reference)
#include <cuda_runtime.h>
#include <math.h>

#define QT 16
#define KT 256
#define TT 2048
#define DD 64
#define HH 16
#define BB 2
#define VSTRIDE 68   // padded V row stride (floats) to spread STS.128 across bank quads

// smem layout (floats):
//   s_scores : QT*TT            = 32768
//   s_kv     : max(64*KT, KT*VSTRIDE) = 17408
//   s_q/s_out: QT*DD            = 1024
#define SMEM_FLOATS (QT*TT + 17408 + QT*DD)

__global__ __launch_bounds__(256, 1)
void attn_fused_kernel(const float* __restrict__ gq, const float* __restrict__ gk,
                       const float* __restrict__ gv, const int* __restrict__ gmask,
                       const float* __restrict__ gbias, float* __restrict__ gout,
                       float* __restrict__ gattn)
{
    extern __shared__ float sm[];
    float* s_scores = sm;                       // [QT][TT]
    float* s_kv     = sm + QT*TT;               // K transposed [64][KT] or V [KT][VSTRIDE]
    float* s_q      = sm + QT*TT + 17408;       // [QT][DD], reused as s_out in PV

    const int t     = threadIdx.x;
    const int qtile = blockIdx.x;
    const int h     = blockIdx.y;
    const int b     = blockIdx.z;
    const int q0    = qtile * QT;

    const float* qbase   = gq + (((size_t)(b*HH + h))*TT + q0) * DD;
    const float* kbase   = gk + ((size_t)(b*HH + h)) * TT * DD;
    const float* vbase   = gv + ((size_t)(b*HH + h)) * TT * DD;
    const float* biasbase= gbias + ((size_t)h * TT + q0) * TT;
    const int*   maskb   = gmask + b * TT;

    // ---- load Q tile: QT*DD = 1024 floats = 256 float4 ----
    ((float4*)s_q)[t] = ((const float4*)qbase)[t];

    // ================= Phase 1: scores = QK^T * scale + bias, masked =================
    const int kg = t & 63;        // k-group: 4 consecutive k per thread
    const int qg = t >> 6;        // q-group: rows {qg, qg+4, qg+8, qg+12}; warp-uniform

    for (int kt_ = 0; kt_ < TT/KT; ++kt_) {
        __syncthreads();
        // load K tile transposed: thread t owns k-row (kt_*KT + t); scatter d-major.
        // STS bank = t mod 32 -> conflict-free.
        {
            const float* krow = kbase + (size_t)(kt_*KT + t) * DD;
            #pragma unroll
            for (int m = 0; m < 16; ++m) {
                float4 f = ((const float4*)krow)[m];
                s_kv[(m*4+0)*KT + t] = f.x;
                s_kv[(m*4+1)*KT + t] = f.y;
                s_kv[(m*4+2)*KT + t] = f.z;
                s_kv[(m*4+3)*KT + t] = f.w;
            }
        }
        __syncthreads();

        float acc[4][4];
        #pragma unroll
        for (int i = 0; i < 4; ++i)
            #pragma unroll
            for (int j = 0; j < 4; ++j) acc[i][j] = 0.f;

        const float* kcol = s_kv + kg*4;
        #pragma unroll 16
        for (int d = 0; d < DD; ++d) {
            float4 k4 = *(const float4*)(kcol + d*KT);
            #pragma unroll
            for (int i = 0; i < 4; ++i) {
                float qv = s_q[(qg + 4*i)*DD + d];   // warp-broadcast
                acc[i][0] = fmaf(qv, k4.x, acc[i][0]);
                acc[i][1] = fmaf(qv, k4.y, acc[i][1]);
                acc[i][2] = fmaf(qv, k4.z, acc[i][2]);
                acc[i][3] = fmaf(qv, k4.w, acc[i][3]);
            }
        }

        // epilogue: scale + bias + mask-replace, store to score tile
        const int kglob = kt_*KT + kg*4;
        const int4 mv = *(const int4*)&maskb[kglob];
        #pragma unroll
        for (int i = 0; i < 4; ++i) {
            const int qr = qg + 4*i;
            float4 bi = *(const float4*)&biasbase[(size_t)qr*TT + kglob];
            float4 r;
            r.x = (mv.x == 0) ? -1e9f : fmaf(acc[i][0], 0.125f, bi.x);
            r.y = (mv.y == 0) ? -1e9f : fmaf(acc[i][1], 0.125f, bi.y);
            r.z = (mv.z == 0) ? -1e9f : fmaf(acc[i][2], 0.125f, bi.z);
            r.w = (mv.w == 0) ? -1e9f : fmaf(acc[i][3], 0.125f, bi.w);
            *(float4*)&s_scores[qr*TT + kglob] = r;
        }
    }
    __syncthreads();

    // zero s_out (aliases s_q; Q no longer needed)
    ((float4*)s_q)[t] = make_float4(0.f, 0.f, 0.f, 0.f);

    // ================= Phase 2: softmax per row + attn store =================
    {
        const int w = t >> 5, l = t & 31;
        for (int r = w; r < QT; r += 8) {
            float* row = s_scores + r*TT;
            float mx = -3.4e38f;
            for (int i = l; i < TT; i += 32) mx = fmaxf(mx, row[i]);
            #pragma unroll
            for (int o = 16; o > 0; o >>= 1)
                mx = fmaxf(mx, __shfl_xor_sync(0xffffffffu, mx, o));
            float sum = 0.f;
            for (int i = l; i < TT; i += 32) {
                float e = __expf(row[i] - mx);
                row[i] = e;
                sum += e;
            }
            #pragma unroll
            for (int o = 16; o > 0; o >>= 1)
                sum += __shfl_xor_sync(0xffffffffu, sum, o);
            const float inv = 1.f / sum;
            __syncwarp();
            float* arow = gattn ? (gattn + (((size_t)(b*HH + h))*TT + q0 + r) * TT) : nullptr;
            for (int i = l*4; i < TT; i += 128) {
                float4 e = *(float4*)&row[i];
                e.x *= inv; e.y *= inv; e.z *= inv; e.w *= inv;
                *(float4*)&row[i] = e;
                if (arow) *(float4*)&arow[i] = e;
            }
        }
    }
    __syncthreads();

    // ================= Phase 3: out = attn @ V =================
    const int dg  = t & 15;          // d4 column
    const int qg2 = (t >> 4) & 3;    // rows {qg2, qg2+4, qg2+8, qg2+12}
    const int kh  = t >> 6;          // k quarter within tile; warp-uniform

    float4 oacc[4];
    #pragma unroll
    for (int i = 0; i < 4; ++i) oacc[i] = make_float4(0.f, 0.f, 0.f, 0.f);

    for (int kt_ = 0; kt_ < TT/KT; ++kt_) {
        __syncthreads();
        // load V tile: thread t owns v-row (kt_*KT + t), natural layout w/ padded stride
        {
            const float* vrow = vbase + (size_t)(kt_*KT + t) * DD;
            #pragma unroll
            for (int m = 0; m < 16; ++m)
                *(float4*)&s_kv[t*VSTRIDE + m*4] = ((const float4*)vrow)[m];
        }
        __syncthreads();

        const int kkbase = kh * 64;
        #pragma unroll 4
        for (int kk = 0; kk < 64; ++kk) {
            float4 v4 = *(const float4*)&s_kv[(kkbase + kk)*VSTRIDE + dg*4];
            const int kgl = kt_*KT + kkbase + kk;
            #pragma unroll
            for (int i = 0; i < 4; ++i) {
                float a = s_scores[(qg2 + 4*i)*TT + kgl];   // warp-broadcast
                oacc[i].x = fmaf(a, v4.x, oacc[i].x);
                oacc[i].y = fmaf(a, v4.y, oacc[i].y);
                oacc[i].z = fmaf(a, v4.z, oacc[i].z);
                oacc[i].w = fmaf(a, v4.w, oacc[i].w);
            }
        }
    }
    __syncthreads();

    // reduce 4 k-quarters into s_out (aliased s_q)
    #pragma unroll
    for (int p = 0; p < 4; ++p) {
        if (kh == p) {
            #pragma unroll
            for (int i = 0; i < 4; ++i) {
                float* dst = &s_q[(qg2 + 4*i)*DD + dg*4];
                float4 cur = *(float4*)dst;
                cur.x += oacc[i].x; cur.y += oacc[i].y;
                cur.z += oacc[i].z; cur.w += oacc[i].w;
                *(float4*)dst = cur;
            }
        }
        __syncthreads();
    }

    // write output tile: 1024 floats = 256 float4, coalesced
    {
        float* obase = gout + (((size_t)(b*HH + h))*TT + q0) * DD;
        ((float4*)obase)[t] = ((float4*)s_q)[t];
    }
}

extern "C" void kernel_launch(void* const* d_in, const int* in_sizes, int n_in,
                              void* d_out, int out_size)
{
    const float* q    = (const float*)d_in[0];
    const float* k    = (const float*)d_in[1];
    const float* v    = (const float*)d_in[2];
    const int*   mask = (const int*)d_in[3];
    const float* bias = (const float*)d_in[4];
    float* out = (float*)d_out;

    const long long O = (long long)BB*HH*TT*DD;       // 4,194,304
    const long long A = (long long)BB*HH*TT*(long long)TT; // 134,217,728
    float* attn = nullptr;
    if ((long long)out_size >= O + A) attn = out + O;

    const size_t smem = SMEM_FLOATS * sizeof(float);  // 204,800 B
    cudaFuncSetAttribute(attn_fused_kernel,
                         cudaFuncAttributeMaxDynamicSharedMemorySize, (int)smem);

    dim3 grid(TT/QT, HH, BB);
    attn_fused_kernel<<<grid, 256, smem>>>(q, k, v, mask, bias, out, attn);
}

// round 2
// speedup vs baseline: 1.0796x; 1.0796x over previous
#include <cuda_runtime.h>
#include <math.h>

#define QT 16
#define KT 256
#define TT 2048
#define DD 64
#define HH 16
#define BB 2
#define SS 2052          // padded score row stride (floats): caps a4 bank conflicts at 2-way
#define VST 68           // padded V row stride (floats)

// smem floats: scores 16*2052=32832 | kv max(64*256, 256*68)=17408 | q 16*64=1024
#define SMEM_FLOATS (QT*SS + 17408 + QT*DD)

__device__ __forceinline__ void ffma2(unsigned long long& d,
                                      unsigned long long a, unsigned long long b) {
    asm("fma.rn.f32x2 %0, %1, %2, %0;" : "+l"(d) : "l"(a), "l"(b));
}
__device__ __forceinline__ unsigned long long dup2(float x) {
    unsigned long long r;
    asm("mov.b64 %0, {%1, %1};" : "=l"(r) : "f"(x));
    return r;
}
__device__ __forceinline__ float2 unpk(unsigned long long v) {
    float2 f;
    asm("mov.b64 {%0, %1}, %2;" : "=f"(f.x), "=f"(f.y) : "l"(v));
    return f;
}

__global__ __launch_bounds__(256, 1)
void attn_fused_kernel(const float* __restrict__ gq, const float* __restrict__ gk,
                       const float* __restrict__ gv, const int* __restrict__ gmask,
                       const float* __restrict__ gbias, float* __restrict__ gout,
                       float* __restrict__ gattn)
{
    extern __shared__ float sm[];
    float* s_scores = sm;                    // [QT][SS]
    float* s_kv     = sm + QT*SS;            // K^T [64][KT]  /  V [KT][VST]
    float* s_q      = sm + QT*SS + 17408;    // [QT][DD]

    const int t     = threadIdx.x;
    const int qtile = blockIdx.x;
    const int h     = blockIdx.y;
    const int b     = blockIdx.z;
    const int q0    = qtile * QT;

    const float* qbase    = gq + (((size_t)(b*HH + h))*TT + q0) * DD;
    const float* kbase    = gk + ((size_t)(b*HH + h)) * TT * DD;
    const float* vbase    = gv + ((size_t)(b*HH + h)) * TT * DD;
    const float* biasbase = gbias + ((size_t)h * TT + q0) * TT;
    const int*   maskb    = gmask + b * TT;

    // ---- load Q tile: 1024 floats = 256 float4 ----
    ((float4*)s_q)[t] = ((const float4*)qbase)[t];

    // ================= Phase 1: scores = QK^T * scale + bias, masked =================
    const int kg = t & 63;        // 4 consecutive k columns
    const int qg = t >> 6;        // rows {qg, qg+4, qg+8, qg+12}; warp-uniform

    for (int kt_ = 0; kt_ < TT/KT; ++kt_) {
        __syncthreads();
        // K tile transposed: thread t owns k-row (kt_*KT + t); STS bank = t%32, conflict-free
        {
            const float* krow = kbase + (size_t)(kt_*KT + t) * DD;
            #pragma unroll
            for (int m = 0; m < 16; ++m) {
                float4 f = ((const float4*)krow)[m];
                s_kv[(m*4+0)*KT + t] = f.x;
                s_kv[(m*4+1)*KT + t] = f.y;
                s_kv[(m*4+2)*KT + t] = f.z;
                s_kv[(m*4+3)*KT + t] = f.w;
            }
        }

        // prefetch bias + mask for this tile (hides L2 latency under compute)
        const int kglob = kt_*KT + kg*4;
        const int4 mv = *(const int4*)&maskb[kglob];
        float4 bi[4];
        #pragma unroll
        for (int i = 0; i < 4; ++i)
            bi[i] = *(const float4*)&biasbase[(size_t)(qg + 4*i)*TT + kglob];

        __syncthreads();

        unsigned long long acc[4][2];
        #pragma unroll
        for (int i = 0; i < 4; ++i) { acc[i][0] = 0ull; acc[i][1] = 0ull; }

        // d blocked into 4 quarters; Q lives in registers per quarter
        #pragma unroll
        for (int db = 0; db < 4; ++db) {
            float qr[4][16];
            #pragma unroll
            for (int i = 0; i < 4; ++i) {
                #pragma unroll
                for (int m = 0; m < 4; ++m) {
                    float4 f = *(const float4*)&s_q[(qg + 4*i)*DD + db*16 + m*4];
                    qr[i][m*4+0] = f.x; qr[i][m*4+1] = f.y;
                    qr[i][m*4+2] = f.z; qr[i][m*4+3] = f.w;
                }
            }
            #pragma unroll
            for (int d = 0; d < 16; ++d) {
                ulonglong2 kk = *(const ulonglong2*)&s_kv[(db*16 + d)*KT + kg*4];
                #pragma unroll
                for (int i = 0; i < 4; ++i) {
                    unsigned long long qq = dup2(qr[i][d]);
                    ffma2(acc[i][0], qq, kk.x);
                    ffma2(acc[i][1], qq, kk.y);
                }
            }
        }

        // epilogue: scale + bias + mask-replace -> padded score tile
        #pragma unroll
        for (int i = 0; i < 4; ++i) {
            const int qr_ = qg + 4*i;
            float2 a01 = unpk(acc[i][0]);
            float2 a23 = unpk(acc[i][1]);
            float4 r;
            r.x = (mv.x == 0) ? -1e9f : fmaf(a01.x, 0.125f, bi[i].x);
            r.y = (mv.y == 0) ? -1e9f : fmaf(a01.y, 0.125f, bi[i].y);
            r.z = (mv.z == 0) ? -1e9f : fmaf(a23.x, 0.125f, bi[i].z);
            r.w = (mv.w == 0) ? -1e9f : fmaf(a23.y, 0.125f, bi[i].w);
            *(float4*)&s_scores[qr_*SS + kglob] = r;
        }
    }
    __syncthreads();

    // ================= Phase 2: softmax per row + attn store =================
    {
        const int w = t >> 5, l = t & 31;
        for (int r = w; r < QT; r += 8) {
            float* row = s_scores + r*SS;
            float mx = -3.4e38f;
            for (int i = l*4; i < TT; i += 128) {
                float4 v = *(const float4*)&row[i];
                mx = fmaxf(mx, fmaxf(fmaxf(v.x, v.y), fmaxf(v.z, v.w)));
            }
            #pragma unroll
            for (int o = 16; o > 0; o >>= 1)
                mx = fmaxf(mx, __shfl_xor_sync(0xffffffffu, mx, o));
            float sum = 0.f;
            for (int i = l*4; i < TT; i += 128) {
                float4 v = *(float4*)&row[i];
                v.x = __expf(v.x - mx); v.y = __expf(v.y - mx);
                v.z = __expf(v.z - mx); v.w = __expf(v.w - mx);
                *(float4*)&row[i] = v;
                sum += (v.x + v.y) + (v.z + v.w);
            }
            #pragma unroll
            for (int o = 16; o > 0; o >>= 1)
                sum += __shfl_xor_sync(0xffffffffu, sum, o);
            const float inv = 1.f / sum;
            __syncwarp();
            float* arow = gattn ? (gattn + (((size_t)(b*HH + h))*TT + q0 + r) * TT) : nullptr;
            for (int i = l*4; i < TT; i += 128) {
                float4 e = *(float4*)&row[i];
                e.x *= inv; e.y *= inv; e.z *= inv; e.w *= inv;
                *(float4*)&row[i] = e;
                if (arow) *(float4*)&arow[i] = e;
            }
        }
    }
    __syncthreads();

    // ================= Phase 3: out = attn @ V =================
    // thread tile: 4 q-rows (4*qg2..+3) x 8 d (dg*8..+7), warp k-split (kh = warp id)
    const int dg  = t & 7;
    const int qg2 = (t >> 3) & 3;
    const int kh  = t >> 5;

    unsigned long long oacc[4][4];
    #pragma unroll
    for (int i = 0; i < 4; ++i)
        #pragma unroll
        for (int j = 0; j < 4; ++j) oacc[i][j] = 0ull;

    for (int kt_ = 0; kt_ < TT/KT; ++kt_) {
        __syncthreads();
        {
            const float* vrow = vbase + (size_t)(kt_*KT + t) * DD;
            #pragma unroll
            for (int m = 0; m < 16; ++m)
                *(float4*)&s_kv[t*VST + m*4] = ((const float4*)vrow)[m];
        }
        __syncthreads();

        #pragma unroll 2
        for (int kc = 0; kc < 8; ++kc) {
            const int k0 = kh*32 + kc*4;
            float a[4][4];
            #pragma unroll
            for (int i = 0; i < 4; ++i) {
                float4 a4 = *(const float4*)&s_scores[(4*qg2 + i)*SS + kt_*KT + k0];
                a[i][0] = a4.x; a[i][1] = a4.y; a[i][2] = a4.z; a[i][3] = a4.w;
            }
            #pragma unroll
            for (int kk = 0; kk < 4; ++kk) {
                ulonglong2 v0 = *(const ulonglong2*)&s_kv[(k0 + kk)*VST + dg*8];
                ulonglong2 v1 = *(const ulonglong2*)&s_kv[(k0 + kk)*VST + dg*8 + 4];
                #pragma unroll
                for (int i = 0; i < 4; ++i) {
                    unsigned long long aa = dup2(a[i][kk]);
                    ffma2(oacc[i][0], aa, v0.x);
                    ffma2(oacc[i][1], aa, v0.y);
                    ffma2(oacc[i][2], aa, v1.x);
                    ffma2(oacc[i][3], aa, v1.y);
                }
            }
        }
    }

    // ---- reduce 8 warp-partials via score smem (free now), then store output ----
    __syncthreads();   // all attn reads done; safe to overwrite s_scores
    {
        float* part = s_scores;   // [8][16][64]
        #pragma unroll
        for (int i = 0; i < 4; ++i) {
            float2 p0 = unpk(oacc[i][0]);
            float2 p1 = unpk(oacc[i][1]);
            float2 p2 = unpk(oacc[i][2]);
            float2 p3 = unpk(oacc[i][3]);
            float* dst = &part[kh*1024 + (4*qg2 + i)*64 + dg*8];
            *(float4*)&dst[0] = make_float4(p0.x, p0.y, p1.x, p1.y);
            *(float4*)&dst[4] = make_float4(p2.x, p2.y, p3.x, p3.y);
        }
    }
    __syncthreads();
    {
        float* part = s_scores;
        const int o = t * 4;      // 1024 outputs, 4 per thread
        float4 s = *(const float4*)&part[o];
        #pragma unroll
        for (int p = 1; p < 8; ++p) {
            float4 x = *(const float4*)&part[p*1024 + o];
            s.x += x.x; s.y += x.y; s.z += x.z; s.w += x.w;
        }
        float* obase = gout + (((size_t)(b*HH + h))*TT + q0) * DD;
        *(float4*)&obase[o] = s;
    }
}

extern "C" void kernel_launch(void* const* d_in, const int* in_sizes, int n_in,
                              void* d_out, int out_size)
{
    const float* q    = (const float*)d_in[0];
    const float* k    = (const float*)d_in[1];
    const float* v    = (const float*)d_in[2];
    const int*   mask = (const int*)d_in[3];
    const float* bias = (const float*)d_in[4];
    float* out = (float*)d_out;

    const long long O = (long long)BB*HH*TT*DD;             // 4,194,304
    const long long A = (long long)BB*HH*TT*(long long)TT;  // 134,217,728
    float* attn = nullptr;
    if ((long long)out_size >= O + A) attn = out + O;

    const size_t smem = SMEM_FLOATS * sizeof(float);        // 205,056 B
    cudaFuncSetAttribute(attn_fused_kernel,
                         cudaFuncAttributeMaxDynamicSharedMemorySize, (int)smem);

    dim3 grid(TT/QT, HH, BB);
    attn_fused_kernel<<<grid, 256, smem>>>(q, k, v, mask, bias, out, attn);
}

// round 3
// speedup vs baseline: 1.2991x; 1.2033x over previous
#include <cuda_runtime.h>
#include <math.h>

#define QT 16
#define KT 256
#define TT 2048
#define DD 64
#define HH 16
#define BB 2
#define VST 68

// per-row softmax stats scratch (device globals are the allowed scratch path)
__device__ float g_m[BB*HH*TT];
__device__ float g_inv[BB*HH*TT];

__device__ __forceinline__ void ffma2(unsigned long long& d,
                                      unsigned long long a, unsigned long long b) {
    asm("fma.rn.f32x2 %0, %1, %2, %0;" : "+l"(d) : "l"(a), "l"(b));
}
__device__ __forceinline__ unsigned long long dup2(float x) {
    unsigned long long r;
    asm("mov.b64 %0, {%1, %1};" : "=l"(r) : "f"(x));
    return r;
}
__device__ __forceinline__ float2 unpk(unsigned long long v) {
    float2 f;
    asm("mov.b64 {%0, %1}, %2;" : "=f"(f.x), "=f"(f.y) : "l"(v));
    return f;
}

// ============== Kernel A: raw scores -> gattn, online (m, sum) -> g_m/g_inv ==============
// smem floats: K^T 64*256 = 16384 | Q 16*64 = 1024 | red 64  => 69,888 B -> 3 CTAs/SM
#define SMEM_A_FLOATS (DD*KT + QT*DD + 64)

__global__ __launch_bounds__(256, 3)
void qk_softmax_kernel(const float* __restrict__ gq, const float* __restrict__ gk,
                       const int* __restrict__ gmask, const float* __restrict__ gbias,
                       float* __restrict__ gattn)
{
    extern __shared__ float sm[];
    float* s_k   = sm;                 // [64][KT] transposed
    float* s_q   = sm + DD*KT;         // [QT][DD]
    float* s_red = s_q + QT*DD;        // [8 warps][4 rows][2]

    const int t  = threadIdx.x;
    const int h  = blockIdx.y, b = blockIdx.z;
    const int q0 = blockIdx.x * QT;

    const float* qbase    = gq + (((size_t)(b*HH + h))*TT + q0) * DD;
    const float* kbase    = gk + ((size_t)(b*HH + h)) * TT * DD;
    const float* biasbase = gbias + ((size_t)h * TT + q0) * TT;
    const int*   maskb    = gmask + b * TT;
    float*       attnbase = gattn + (((size_t)(b*HH + h))*TT + q0) * TT;

    ((float4*)s_q)[t] = ((const float4*)qbase)[t];

    const int kg = t & 63;      // 4 consecutive k
    const int qg = t >> 6;      // rows {qg+4i}; uniform within warp

    float mr[4], sr[4];
    #pragma unroll
    for (int i = 0; i < 4; ++i) { mr[i] = -3.4e38f; sr[i] = 0.f; }

    for (int kt_ = 0; kt_ < TT/KT; ++kt_) {
        __syncthreads();
        {   // K tile transposed: thread t owns k-row; STS bank = t%32, conflict-free
            const float* krow = kbase + (size_t)(kt_*KT + t) * DD;
            #pragma unroll
            for (int m = 0; m < 16; ++m) {
                float4 f = ((const float4*)krow)[m];
                s_k[(m*4+0)*KT + t] = f.x;
                s_k[(m*4+1)*KT + t] = f.y;
                s_k[(m*4+2)*KT + t] = f.z;
                s_k[(m*4+3)*KT + t] = f.w;
            }
        }
        const int kglob = kt_*KT + kg*4;
        const int4 mv = *(const int4*)&maskb[kglob];
        float4 bi[4];
        #pragma unroll
        for (int i = 0; i < 4; ++i)
            bi[i] = *(const float4*)&biasbase[(size_t)(qg + 4*i)*TT + kglob];
        __syncthreads();

        unsigned long long acc[4][2];
        #pragma unroll
        for (int i = 0; i < 4; ++i) { acc[i][0] = 0ull; acc[i][1] = 0ull; }

        #pragma unroll
        for (int db = 0; db < 16; ++db) {       // 4 d per step; Q refreshed per step
            float qf[4][4];
            #pragma unroll
            for (int i = 0; i < 4; ++i) {
                float4 f = *(const float4*)&s_q[(qg + 4*i)*DD + db*4];
                qf[i][0] = f.x; qf[i][1] = f.y; qf[i][2] = f.z; qf[i][3] = f.w;
            }
            #pragma unroll
            for (int dd = 0; dd < 4; ++dd) {
                ulonglong2 kk = *(const ulonglong2*)&s_k[(db*4 + dd)*KT + kg*4];
                #pragma unroll
                for (int i = 0; i < 4; ++i) {
                    unsigned long long qq = dup2(qf[i][dd]);
                    ffma2(acc[i][0], qq, kk.x);
                    ffma2(acc[i][1], qq, kk.y);
                }
            }
        }

        // epilogue: scale+bias+mask -> raw scores to gmem; online (m,s)
        #pragma unroll
        for (int i = 0; i < 4; ++i) {
            float2 a01 = unpk(acc[i][0]);
            float2 a23 = unpk(acc[i][1]);
            float4 r;
            r.x = (mv.x == 0) ? -1e9f : fmaf(a01.x, 0.125f, bi[i].x);
            r.y = (mv.y == 0) ? -1e9f : fmaf(a01.y, 0.125f, bi[i].y);
            r.z = (mv.z == 0) ? -1e9f : fmaf(a23.x, 0.125f, bi[i].z);
            r.w = (mv.w == 0) ? -1e9f : fmaf(a23.y, 0.125f, bi[i].w);
            *(float4*)&attnbase[(size_t)(qg + 4*i)*TT + kglob] = r;

            float tmax = fmaxf(fmaxf(r.x, r.y), fmaxf(r.z, r.w));
            float mn = fmaxf(mr[i], tmax);
            float c  = __expf(mr[i] - mn);
            sr[i] = sr[i]*c + (__expf(r.x - mn) + __expf(r.y - mn))
                            + (__expf(r.z - mn) + __expf(r.w - mn));
            mr[i] = mn;
        }
    }

    // reduce (m,s) across 32 lanes (all lanes in a warp share the same 4 rows)
    const int lane = t & 31, w = t >> 5;
    #pragma unroll
    for (int i = 0; i < 4; ++i) {
        #pragma unroll
        for (int o = 16; o > 0; o >>= 1) {
            float mo = __shfl_xor_sync(0xffffffffu, mr[i], o);
            float so = __shfl_xor_sync(0xffffffffu, sr[i], o);
            float mn = fmaxf(mr[i], mo);
            sr[i] = sr[i]*__expf(mr[i]-mn) + so*__expf(mo-mn);
            mr[i] = mn;
        }
        if (lane == 0) { s_red[w*8 + i*2] = mr[i]; s_red[w*8 + i*2 + 1] = sr[i]; }
    }
    __syncthreads();
    if (t < 16) {   // combine the 2 warps per qg group
        const int qgr = t & 3, i = t >> 2;
        float m0 = s_red[(2*qgr  )*8 + i*2], s0 = s_red[(2*qgr  )*8 + i*2 + 1];
        float m1 = s_red[(2*qgr+1)*8 + i*2], s1 = s_red[(2*qgr+1)*8 + i*2 + 1];
        float mn = fmaxf(m0, m1);
        float s  = s0*__expf(m0-mn) + s1*__expf(m1-mn);
        size_t gi = (size_t)(b*HH + h)*TT + q0 + qgr + 4*i;
        g_m[gi] = mn; g_inv[gi] = 1.f / s;
    }
}

// ============== Kernel B: normalize attn in-place + out = attn @ V ==============
// smem floats: V 256*68 = 17408 => 69,632 B -> 3 CTAs/SM
#define SMEM_B_FLOATS (KT*VST)

__global__ __launch_bounds__(256, 3)
void pv_kernel(const float* __restrict__ gv, float* __restrict__ gattn,
               float* __restrict__ gout)
{
    extern __shared__ float sm[];
    float* s_v = sm;   // [KT][VST]; reused for output reduction at the end

    const int t  = threadIdx.x;
    const int h  = blockIdx.y, b = blockIdx.z;
    const int q0 = blockIdx.x * QT;

    const float* vbase    = gv + ((size_t)(b*HH + h)) * TT * DD;
    float*       attnbase = gattn + (((size_t)(b*HH + h))*TT + q0) * TT;

    // normalize mapping: rows qgN + 4i, cols (t&63)*4
    const int qgN = t >> 6;
    float m4[4], inv4[4];
    {
        const size_t statb = (size_t)(b*HH + h)*TT + q0;
        #pragma unroll
        for (int i = 0; i < 4; ++i) {
            m4[i]   = g_m[statb + qgN + 4*i];
            inv4[i] = g_inv[statb + qgN + 4*i];
        }
    }

    // PV mapping: 4 rows (4*qg2+i) x 8 d (dg*8..), warp k-split kh
    const int dg  = t & 7;
    const int qg2 = (t >> 3) & 3;
    const int kh  = t >> 5;

    unsigned long long oacc[4][4];
    #pragma unroll
    for (int i = 0; i < 4; ++i)
        #pragma unroll
        for (int j = 0; j < 4; ++j) oacc[i][j] = 0ull;

    const int colbase = (t & 63) * 4;

    for (int kt_ = 0; kt_ < TT/KT; ++kt_) {
        __syncthreads();
        {   // V tile
            const float* vrow = vbase + (size_t)(kt_*KT + t) * DD;
            #pragma unroll
            for (int m = 0; m < 16; ++m)
                *(float4*)&s_v[t*VST + m*4] = ((const float4*)vrow)[m];
        }
        // normalize this score tile in-place (overlaps V-store latency)
        #pragma unroll
        for (int i = 0; i < 4; ++i) {
            float* p = attnbase + (size_t)(qgN + 4*i)*TT + kt_*KT + colbase;
            float4 x = *(const float4*)p;
            x.x = __expf(x.x - m4[i]) * inv4[i];
            x.y = __expf(x.y - m4[i]) * inv4[i];
            x.z = __expf(x.z - m4[i]) * inv4[i];
            x.w = __expf(x.w - m4[i]) * inv4[i];
            *(float4*)p = x;
        }
        __syncthreads();   // V in smem + normalized p visible block-wide

        #pragma unroll 2
        for (int kc = 0; kc < 8; ++kc) {
            const int k0 = kh*32 + kc*4;
            float a[4][4];
            #pragma unroll
            for (int i = 0; i < 4; ++i) {
                float4 a4 = *(const float4*)&attnbase[(size_t)(4*qg2 + i)*TT + kt_*KT + k0];
                a[i][0] = a4.x; a[i][1] = a4.y; a[i][2] = a4.z; a[i][3] = a4.w;
            }
            #pragma unroll
            for (int kk = 0; kk < 4; ++kk) {
                ulonglong2 v0 = *(const ulonglong2*)&s_v[(k0 + kk)*VST + dg*8];
                ulonglong2 v1 = *(const ulonglong2*)&s_v[(k0 + kk)*VST + dg*8 + 4];
                #pragma unroll
                for (int i = 0; i < 4; ++i) {
                    unsigned long long aa = dup2(a[i][kk]);
                    ffma2(oacc[i][0], aa, v0.x);
                    ffma2(oacc[i][1], aa, v0.y);
                    ffma2(oacc[i][2], aa, v1.x);
                    ffma2(oacc[i][3], aa, v1.y);
                }
            }
        }
    }

    // reduce 8 warp k-split partials via smem (s_v is free now)
    __syncthreads();
    #pragma unroll
    for (int i = 0; i < 4; ++i) {
        float2 p0 = unpk(oacc[i][0]);
        float2 p1 = unpk(oacc[i][1]);
        float2 p2 = unpk(oacc[i][2]);
        float2 p3 = unpk(oacc[i][3]);
        float* dst = &s_v[kh*1024 + (4*qg2 + i)*64 + dg*8];
        *(float4*)&dst[0] = make_float4(p0.x, p0.y, p1.x, p1.y);
        *(float4*)&dst[4] = make_float4(p2.x, p2.y, p3.x, p3.y);
    }
    __syncthreads();
    {
        const int o = t * 4;
        float4 s = *(const float4*)&s_v[o];
        #pragma unroll
        for (int p = 1; p < 8; ++p) {
            float4 x = *(const float4*)&s_v[p*1024 + o];
            s.x += x.x; s.y += x.y; s.z += x.z; s.w += x.w;
        }
        float* obase = gout + (((size_t)(b*HH + h))*TT + q0) * DD;
        *(float4*)&obase[o] = s;
    }
}

extern "C" void kernel_launch(void* const* d_in, const int* in_sizes, int n_in,
                              void* d_out, int out_size)
{
    const float* q    = (const float*)d_in[0];
    const float* k    = (const float*)d_in[1];
    const float* v    = (const float*)d_in[2];
    const int*   mask = (const int*)d_in[3];
    const float* bias = (const float*)d_in[4];
    float* out  = (float*)d_out;
    float* attn = out + (long long)BB*HH*TT*DD;   // second output region

    cudaFuncSetAttribute(qk_softmax_kernel,
        cudaFuncAttributeMaxDynamicSharedMemorySize, (int)(SMEM_A_FLOATS*sizeof(float)));
    cudaFuncSetAttribute(pv_kernel,
        cudaFuncAttributeMaxDynamicSharedMemorySize, (int)(SMEM_B_FLOATS*sizeof(float)));

    dim3 grid(TT/QT, HH, BB);
    qk_softmax_kernel<<<grid, 256, SMEM_A_FLOATS*sizeof(float)>>>(q, k, mask, bias, attn);
    pv_kernel<<<grid, 256, SMEM_B_FLOATS*sizeof(float)>>>(v, attn, out);
}